// round 7
// baseline (speedup 1.0000x reference)
#include <cuda_runtime.h>

// Shapes fixed by the dataset
#define NN   8192
#define D    128
#define PP   256
#define KK   256
#define DEGN 32
#define FFN  16
#define TEMP_INV (1.0f/0.07f)
#define NB_TERM (PP * 2)          // 2 blocks per p, 8 warps, 2 j per warp
#define NB_NEG  (KK / 16)         // 16 negatives per block (2 per warp)
#define GRID    (NB_TERM + NB_NEG)

// Scratch (no allocations allowed)
__device__ __align__(16) float g_zq[D];          // normalized z[query]
__device__ __align__(16) float g_znx[DEGN * D];  // normalized z[N(q)]
__device__ float  g_te[DEGN];         // query-side time encodings
__device__ float  g_core_sum;
__device__ float4 g_part[16 * PP];    // [jg][p], jg = j-pair group (0..15)
__device__ float  g_pos[PP];
__device__ float  g_neg[KK];
__device__ unsigned int g_ctr;        // reset by k0 each launch

__device__ __forceinline__ float warpSum(float v) {
#pragma unroll
    for (int o = 16; o; o >>= 1) v += __shfl_xor_sync(0xffffffffu, v, o);
    return v;
}
__device__ __forceinline__ float halfSum(float v) {
#pragma unroll
    for (int o = 8; o; o >>= 1) v += __shfl_xor_sync(0xffffffffu, v, o);
    return v;
}
__device__ __forceinline__ float dot4(float4 a, float4 b) {
    return a.x*b.x + a.y*b.y + a.z*b.z + a.w*b.w;
}
__device__ __forceinline__ unsigned int ctrAddRelease(unsigned int* p) {
    unsigned int old;
    asm volatile("atom.add.release.gpu.global.u32 %0, [%1], 1;"
                 : "=r"(old) : "l"(p) : "memory");
    return old;
}

// ---------------------------------------------------------------------------
// k0: hoist ALL p-invariant work (1 block x 1024 threads, warp-parallel)
// ---------------------------------------------------------------------------
__global__ void __launch_bounds__(1024) k0_setup(
        const float* __restrict__ z,
        const float* __restrict__ edge_times,
        const float* __restrict__ cur_t,
        const float* __restrict__ core,
        const float* __restrict__ omega,
        const float* __restrict__ phi,
        const int*   __restrict__ qidx,
        const int*   __restrict__ nbr_idxs,
        const int*   __restrict__ neighbors)
{
    __shared__ float red[32];
    const int tid = threadIdx.x;
    const int lane = tid & 31, warp = tid >> 5;
    const int q = qidx[0];
    const float ct = cur_t[0];

    if (tid == 0) g_ctr = 0;

    // warp 0: normalized z_q
    if (warp == 0) {
        float4 v = ((const float4*)(z + (size_t)q * D))[lane];
        float inv = rsqrtf(warpSum(dot4(v, v)));
        ((float4*)g_zq)[lane] = make_float4(v.x*inv, v.y*inv, v.z*inv, v.w*inv);
    }

    // warp w: normalized row N(q)[w] + te1[w]
    const int idx = neighbors[q * DEGN + warp];
    {
        float4 r = ((const float4*)(z + (size_t)idx * D))[lane];
        float inv = rsqrtf(warpSum(dot4(r, r)));
        ((float4*)g_znx)[warp * 32 + lane] =
            make_float4(r.x*inv, r.y*inv, r.z*inv, r.w*inv);
    }
    {
        float dt = 0.f;
        if (lane == 0) dt = ct - edge_times[(size_t)q * NN + idx];
        dt = __shfl_sync(0xffffffffu, dt, 0);
        float c = 0.f;
        if (lane == 0)       c = omega[0] * dt + phi[0];
        else if (lane < FFN) c = __sinf(omega[lane] * dt + phi[lane]);
        float te = warpSum(c);
        if (lane == 0) g_te[warp] = te;
    }

    // core proximity sum (threads 0..255)
    {
        float cd = 0.f;
        if (tid < PP) cd = core[nbr_idxs[tid]] - core[q];
        float cs = warpSum(cd * cd);
        if (lane == 0) red[warp] = cs;
        __syncthreads();
        if (tid == 0) {
            float t = 0.f;
            for (int i = 0; i < 8; i++) t += red[i];
            g_core_sum = t;
        }
    }
}

// ---------------------------------------------------------------------------
// k1: term blocks (b < NB_TERM): p = b>>1, warp handles j = ja and ja+8.
// Neg blocks: 2 negatives per warp. Last block folds the scalar reduction.
// ---------------------------------------------------------------------------
__global__ void __launch_bounds__(256)
k1_main(const float* __restrict__ z,
        const float* __restrict__ edge_times,
        const float* __restrict__ cur_t,
        const float* __restrict__ omega,
        const float* __restrict__ phi,
        const int*   __restrict__ neg_idxs,
        const int*   __restrict__ nbr_idxs,
        const int*   __restrict__ neighbors,
        float* __restrict__ out)
{
    __shared__ float s_fr[3][8];
    __shared__ unsigned int s_islast;

    const int tid  = threadIdx.x;
    const int lane = tid & 31, warp = tid >> 5;
    const int b    = blockIdx.x;
    const float ct = cur_t[0];

    if (b < NB_TERM) {
        const int p    = b >> 1;
        const int half = b & 1;
        const int ja   = half * 16 + warp;      // first j
        const int jb   = ja + 8;                // second j
        const int nbp  = nbr_idxs[p];           // broadcast

        // two independent depth-3 chains + amortized shared rows
        const int idxa = neighbors[nbp * DEGN + ja];
        const int idxb = neighbors[nbp * DEGN + jb];
        const float eta = edge_times[(size_t)nbp * NN + idxa];
        const float etb = edge_times[(size_t)nbp * NN + idxb];

        const float4 ra = ((const float4*)(z + (size_t)idxa * D))[lane];
        const float4 rb = ((const float4*)(z + (size_t)idxb * D))[lane];
        const float4 vb = ((const float4*)(z + (size_t)nbp  * D))[lane];
        const float4 zq = ((const float4*)g_zq)[lane];           // unit
        const float4 xa = ((const float4*)g_znx)[ja * 32 + lane]; // unit
        const float4 xb = ((const float4*)g_znx)[jb * 32 + lane]; // unit
        const float te1a = g_te[ja];
        const float te1b = g_te[jb];

        // neighbor-side time encodings: lanes 0-15 -> ja, 16-31 -> jb
        const int   f  = lane & 15;
        const float dt = (lane < 16) ? (ct - eta) : (ct - etb);
        float c = (f == 0) ? (omega[0] * dt + phi[0])
                           : __sinf(omega[f] * dt + phi[f]);

        // independent butterflies (ILP-overlapped)
        float ssb  = warpSum(dot4(vb, vb));
        float d1a  = warpSum(dot4(xa, vb));
        float d1b  = warpSum(dot4(xb, vb));
        float ssra = warpSum(dot4(ra, ra));
        float ssrb = warpSum(dot4(rb, rb));
        float d2a  = warpSum(dot4(ra, zq));
        float d2b  = warpSum(dot4(rb, zq));
        float hc   = halfSum(c);
        const float te2a = __shfl_sync(0xffffffffu, hc, 0);
        const float te2b = __shfl_sync(0xffffffffu, hc, 16);

        const float invb = rsqrtf(ssb);
        const float mu1a = 2.f * d1a * invb - 2.f;
        const float mu1b = 2.f * d1b * invb - 2.f;
        const float w1a  = __expf(mu1a * TEMP_INV - te1a);
        const float w1b  = __expf(mu1b * TEMP_INV - te1b);
        const float mu2a = 2.f * d2a * rsqrtf(ssra) - 2.f;
        const float mu2b = 2.f * d2b * rsqrtf(ssrb) - 2.f;
        const float w2a  = __expf(mu2a * TEMP_INV - te2a);
        const float w2b  = __expf(mu2b * TEMP_INV - te2b);

        if (lane == 0)
            g_part[(half * 8 + warp) * PP + p] =
                make_float4(w1a + w1b,
                            w1a * mu1a + w1b * mu1b,
                            w2a + w2b,
                            w2a * mu2a + w2b * mu2b);

        if (half == 0 && warp == 0) {
            float dqb = warpSum(dot4(vb, zq));
            if (lane == 0) {
                float muxy = 2.f * dqb * invb - 2.f;
                float sgm  = 1.f / (1.f + __expf(-muxy));
                g_pos[p] = -__logf(sgm + 1e-8f);
            }
        }
    } else {
        // neg blocks: warp handles negatives ka, ka+1
        const int ka = (b - NB_TERM) * 16 + warp * 2;
        const int na = neg_idxs[ka];
        const int nb2 = neg_idxs[ka + 1];
        const float4 va = ((const float4*)(z + (size_t)na  * D))[lane];
        const float4 vb = ((const float4*)(z + (size_t)nb2 * D))[lane];
        const float4 zq = ((const float4*)g_zq)[lane];            // unit
        float ssa = warpSum(dot4(va, va));
        float ssb = warpSum(dot4(vb, vb));
        float da  = warpSum(dot4(va, zq));
        float db  = warpSum(dot4(vb, zq));
        if (lane == 0) {
            float mua = 2.f * da * rsqrtf(ssa) - 2.f;
            float mub = 2.f * db * rsqrtf(ssb) - 2.f;
            g_neg[ka]     = -__logf(1.f - 1.f / (1.f + __expf(-mua)) + 1e-8f);
            g_neg[ka + 1] = -__logf(1.f - 1.f / (1.f + __expf(-mub)) + 1e-8f);
        }
    }

    // ---- last-block gate ----
    __syncthreads();
    if (tid == 0) {
        unsigned int t = ctrAddRelease(&g_ctr);
        s_islast = (t == (unsigned int)(GRID - 1));
    }
    __syncthreads();
    if (s_islast) {
        // thread tid owns p = tid (and negative k = tid); coalesced reads
        float W1 = 0.f, WM1 = 0.f, W2 = 0.f, WM2 = 0.f;
#pragma unroll
        for (int jg = 0; jg < 16; jg++) {
            float4 a = __ldcg(&g_part[jg * PP + tid]);
            W1 += a.x; WM1 += a.y; W2 += a.z; WM2 += a.w;
        }
        float term1 = WM1 / (W1 + 1e-8f);
        float term2 = WM2 / (W2 + 1e-8f);
        float d  = term1 + term2;            // lambda_T - lambda_S
        float ad = fabsf(d);
        float al = (ad < 1.f) ? 0.5f * d * d : ad - 0.5f;

        float a  = warpSum(al);
        float sp = warpSum(__ldcg(g_pos + tid));
        float sn = warpSum(__ldcg(g_neg + tid));
        if (lane == 0) {
            s_fr[0][warp] = a; s_fr[1][warp] = sp; s_fr[2][warp] = sn;
        }
        __syncthreads();
        if (tid == 0) {
            float A = 0.f, P = 0.f, Ng = 0.f;
#pragma unroll
            for (int i = 0; i < 8; i++) {
                A += s_fr[0][i]; P += s_fr[1][i]; Ng += s_fr[2][i];
            }
            out[0] = P / PP + Ng / KK
                   + 0.1f * (g_core_sum / PP)
                   + 0.1f * (A / PP);
            g_ctr = 0;   // belt-and-suspenders (k0 also resets)
        }
    }
}

// ---------------------------------------------------------------------------
extern "C" void kernel_launch(void* const* d_in, const int* in_sizes, int n_in,
                              void* d_out, int out_size)
{
    const float* z          = (const float*)d_in[0];
    const float* edge_times = (const float*)d_in[1];
    const float* cur_t      = (const float*)d_in[2];
    const float* core       = (const float*)d_in[3];
    const float* omega      = (const float*)d_in[4];
    const float* phi        = (const float*)d_in[5];
    const int*   qidx       = (const int*)d_in[6];
    const int*   neg_idxs   = (const int*)d_in[7];
    const int*   nbr_idxs   = (const int*)d_in[8];
    const int*   neighbors  = (const int*)d_in[9];

    k0_setup<<<1, 1024>>>(z, edge_times, cur_t, core, omega, phi,
                          qidx, nbr_idxs, neighbors);
    k1_main<<<GRID, 256>>>(z, edge_times, cur_t, omega, phi,
                           neg_idxs, nbr_idxs, neighbors, (float*)d_out);
}